// round 9
// baseline (speedup 1.0000x reference)
#include <cuda_runtime.h>
#include <cuda_bf16.h>
#include <math.h>
#include <stdint.h>

#define N_NODES   8192
#define C_IN      256
#define C_OUT     128
#define NEG_SLOPE 0.2f
#define MAX_DEG   128

#define BM 32
#define BK 16
#define GEMM_BLOCKS (N_NODES / BM)     // 256
#define SCAN_TOTAL  1024               // column-stripe blocks (8 cols each)
#define COLS_PER_BLK 8

// -------- scratch (__device__ globals; zero-initialized at module load) ----
__device__ float g_h[N_NODES * C_OUT];      // 4 MB, h = x @ W
__device__ float g_asrc[N_NODES];
__device__ float g_adst[N_NODES];
__device__ int   g_done;                    // GEMM completion counter
__device__ int   g_fin;                     // scan-block completion counter

#define FULLM 0xFFFFFFFFu

// ---------------------------------------------------------------------
// ONE kernel does everything.
//  blocks [0, 256):      h = x@W (4x4 micro-tile) + attention scores,
//                        then release g_done.
//  blocks [256, 1280):   own an 8-column stripe of adj (32B x 8192 rows).
//                        Stream the stripe (DRAM-bound), building the
//                        complete per-column edge lists in SMEM (no global
//                        atomics). Then wait for g_done (GEMM finishes
//                        ~20us, stripe read ~40us -> wait is ~free) and
//                        aggregate those 8 columns directly. Aggregation
//                        (L2-bound) overlaps other blocks' stripe reads
//                        (DRAM-bound) chip-wide.
// g_done/g_fin self-reset at the end -> graph-replay idempotent.
// ---------------------------------------------------------------------
__global__ __launch_bounds__(256, 5) void fused_all_kernel(
    const float* __restrict__ x, const float* __restrict__ W,
    const float* __restrict__ adj,
    const float* __restrict__ att_src, const float* __restrict__ att_dst,
    const float* __restrict__ bias, float* __restrict__ out) {

    __shared__ union USm {
        struct { float xs[BK][BM]; float ws[BK][C_OUT]; } g;              // 10 KB
        struct { unsigned short list[COLS_PER_BLK][MAX_DEG];              // 2 KB
                 float ew[COLS_PER_BLK][MAX_DEG];                         // 4 KB
                 int cnt[COLS_PER_BLK]; } s;
    } su;

    int tid = threadIdx.x;

    if (blockIdx.x < GEMM_BLOCKS) {
        // ================= GEMM (BM=32, 4x4 micro-tile) + attention ==========
        int row0 = blockIdx.x * BM;
        int tx = tid & 31;   // channel group: c = tx*4
        int ty = tid >> 5;   // row group: rows ty*4 .. ty*4+3

        float acc[4][4];
#pragma unroll
        for (int r = 0; r < 4; r++)
#pragma unroll
            for (int c = 0; c < 4; c++) acc[r][c] = 0.0f;

        for (int k0 = 0; k0 < C_IN; k0 += BK) {
            {   // x tile: 32 rows x 16 k, one float2 per thread
                int r  = tid >> 3;
                int kk = (tid & 7) * 2;
                float2 v = *reinterpret_cast<const float2*>(
                    &x[(row0 + r) * C_IN + k0 + kk]);
                su.g.xs[kk + 0][r] = v.x; su.g.xs[kk + 1][r] = v.y;
            }
            {   // W tile: 16 k x 128 c, two float4 per thread
                int kk = tid >> 5;
                int c  = (tid & 31) * 4;
                *reinterpret_cast<float4*>(&su.g.ws[kk][c]) =
                    *reinterpret_cast<const float4*>(&W[(k0 + kk) * C_OUT + c]);
                *reinterpret_cast<float4*>(&su.g.ws[kk + 8][c]) =
                    *reinterpret_cast<const float4*>(&W[(k0 + kk + 8) * C_OUT + c]);
            }
            __syncthreads();
#pragma unroll
            for (int kk = 0; kk < BK; kk++) {
                float4 b = *reinterpret_cast<const float4*>(&su.g.ws[kk][tx * 4]);
#pragma unroll
                for (int r = 0; r < 4; r++) {
                    float a = su.g.xs[kk][ty * 4 + r];
                    acc[r][0] += a * b.x;
                    acc[r][1] += a * b.y;
                    acc[r][2] += a * b.z;
                    acc[r][3] += a * b.w;
                }
            }
            __syncthreads();
        }

        float4 as = *reinterpret_cast<const float4*>(&att_src[tx * 4]);
        float4 ad = *reinterpret_cast<const float4*>(&att_dst[tx * 4]);

#pragma unroll
        for (int r = 0; r < 4; r++) {
            int row = row0 + ty * 4 + r;
            float4 v = make_float4(acc[r][0], acc[r][1], acc[r][2], acc[r][3]);
            *reinterpret_cast<float4*>(&g_h[row * C_OUT + tx * 4]) = v;

            float s = v.x * as.x + v.y * as.y + v.z * as.z + v.w * as.w;
            float d = v.x * ad.x + v.y * ad.y + v.z * ad.z + v.w * ad.w;
#pragma unroll
            for (int o = 16; o > 0; o >>= 1) {
                s += __shfl_xor_sync(FULLM, s, o);
                d += __shfl_xor_sync(FULLM, d, o);
            }
            if (tx == 0) { g_asrc[row] = s; g_adst[row] = d; }
        }

        __threadfence();          // make h / asrc / adst visible device-wide
        __syncthreads();
        if (tid == 0) atomicAdd(&g_done, 1);
        return;
    }

    // ================= column-stripe scan + in-block aggregate =================
    const int sb    = blockIdx.x - GEMM_BLOCKS;   // 0..1023
    const int jbase = sb * COLS_PER_BLK;

    if (tid < COLS_PER_BLK) su.s.cnt[tid] = 0;
    __syncthreads();

    {   // stream the 32B x 8192-row stripe; batch-8 independent LDG.128
        const int half = tid & 1;       // which 16B of the 32B stripe
        const int r0   = tid >> 1;      // 0..127
        const float* colp = adj + jbase + half * 4;

#pragma unroll 1
        for (int it = 0; it < 8; it++) {
            uint4 v[8];
#pragma unroll
            for (int k = 0; k < 8; k++) {
                int r = (it * 8 + k) * 128 + r0;
                v[k] = __ldcs(reinterpret_cast<const uint4*>(
                    colp + (long)r * N_NODES));
            }
#pragma unroll
            for (int k = 0; k < 8; k++) {
                uint4 vk = v[k];
                if ((vk.x | vk.y | vk.z | vk.w) == 0u) continue;
                int r = (it * 8 + k) * 128 + r0;
                unsigned int b[4] = {vk.x, vk.y, vk.z, vk.w};
#pragma unroll
                for (int e = 0; e < 4; e++) {
                    if (b[e] != 0u) {
                        int jloc = half * 4 + e;
                        if (r != jbase + jloc) {   // self-loop added later
                            int pos = atomicAdd(&su.s.cnt[jloc], 1);
                            if (pos < MAX_DEG)
                                su.s.list[jloc][pos] = (unsigned short)r;
                        }
                    }
                }
            }
        }
    }
    __syncthreads();

    // wait for GEMM results (almost always already done)
    if (tid == 0) {
        while (atomicAdd(&g_done, 0) < GEMM_BLOCKS) __nanosleep(64);
        __threadfence();
    }
    __syncthreads();

    // -------- aggregate: warp w handles column jbase + w --------
    int w    = tid >> 5;
    int lane = tid & 31;
    int j    = jbase + w;

    int cnt = su.s.cnt[w];
    if (cnt > MAX_DEG) cnt = MAX_DEG;
    float adst_j = g_adst[j];

    // exp weights into smem + partial sum
    float partial = 0.0f;
    for (int d = lane; d < cnt; d += 32) {
        int i = su.s.list[w][d];
        float z = g_asrc[i] + adst_j;
        z = (z > 0.0f) ? z : NEG_SLOPE * z;
        float e = __expf(z);
        su.s.ew[w][d] = e;
        partial += e;
    }
#pragma unroll
    for (int o = 16; o > 0; o >>= 1) partial += __shfl_xor_sync(FULLM, partial, o);
    __syncwarp();

    // self-loop (reference SETS the diagonal to 1 -> always present)
    float zs = g_asrc[j] + adst_j;
    zs = (zs > 0.0f) ? zs : NEG_SLOPE * zs;
    float es  = __expf(zs);
    float inv = 1.0f / (partial + es);

    float4 hj = reinterpret_cast<const float4*>(&g_h[j * C_OUT])[lane];
    float4 acc0 = make_float4(es * hj.x, es * hj.y, es * hj.z, es * hj.w);
    float4 acc1 = make_float4(0.f, 0.f, 0.f, 0.f);

    int d = 0;
    for (; d + 4 <= cnt; d += 4) {
        float e0 = su.s.ew[w][d],     e1 = su.s.ew[w][d + 1];
        float e2 = su.s.ew[w][d + 2], e3 = su.s.ew[w][d + 3];
        int i0 = su.s.list[w][d],     i1 = su.s.list[w][d + 1];
        int i2 = su.s.list[w][d + 2], i3 = su.s.list[w][d + 3];
        float4 a  = reinterpret_cast<const float4*>(&g_h[i0 * C_OUT])[lane];
        float4 b  = reinterpret_cast<const float4*>(&g_h[i1 * C_OUT])[lane];
        float4 cc = reinterpret_cast<const float4*>(&g_h[i2 * C_OUT])[lane];
        float4 dd = reinterpret_cast<const float4*>(&g_h[i3 * C_OUT])[lane];
        acc0.x += e0 * a.x;  acc0.y += e0 * a.y;  acc0.z += e0 * a.z;  acc0.w += e0 * a.w;
        acc1.x += e1 * b.x;  acc1.y += e1 * b.y;  acc1.z += e1 * b.z;  acc1.w += e1 * b.w;
        acc0.x += e2 * cc.x; acc0.y += e2 * cc.y; acc0.z += e2 * cc.z; acc0.w += e2 * cc.w;
        acc1.x += e3 * dd.x; acc1.y += e3 * dd.y; acc1.z += e3 * dd.z; acc1.w += e3 * dd.w;
    }
    for (; d < cnt; d++) {
        float e = su.s.ew[w][d];
        int  i  = su.s.list[w][d];
        float4 a = reinterpret_cast<const float4*>(&g_h[i * C_OUT])[lane];
        acc0.x += e * a.x; acc0.y += e * a.y; acc0.z += e * a.z; acc0.w += e * a.w;
    }

    float4 bv = reinterpret_cast<const float4*>(bias)[lane];
    float4 o;
    o.x = (acc0.x + acc1.x) * inv + bv.x;
    o.y = (acc0.y + acc1.y) * inv + bv.y;
    o.z = (acc0.z + acc1.z) * inv + bv.z;
    o.w = (acc0.w + acc1.w) * inv + bv.w;
    reinterpret_cast<float4*>(&out[j * C_OUT])[lane] = o;

    // -------- self-reset of flags for the next graph replay --------
    __syncthreads();
    if (tid == 0) {
        int f = atomicAdd(&g_fin, 1);
        if (f == SCAN_TOTAL - 1) {      // last scan block: everyone passed the spin
            atomicExch(&g_fin, 0);
            atomicExch(&g_done, 0);
            __threadfence();
        }
    }
}

// ---------------------------------------------------------------------
extern "C" void kernel_launch(void* const* d_in, const int* in_sizes, int n_in,
                              void* d_out, int out_size) {
    const float* x       = (const float*)d_in[0];
    const float* adj     = (const float*)d_in[1];
    const float* W       = (const float*)d_in[2];
    const float* att_src = (const float*)d_in[3];
    const float* att_dst = (const float*)d_in[4];
    const float* bias    = (const float*)d_in[5];
    float* out = (float*)d_out;

    fused_all_kernel<<<GEMM_BLOCKS + SCAN_TOTAL, 256>>>(
        x, W, adj, att_src, att_dst, bias, out);
}

// round 10
// speedup vs baseline: 1.4322x; 1.4322x over previous
#include <cuda_runtime.h>
#include <cuda_bf16.h>
#include <math.h>
#include <stdint.h>

#define N_NODES   8192
#define C_IN      256
#define C_OUT     128
#define NEG_SLOPE 0.2f
#define MAX_DEG   128

#define BM 32
#define BK 16
#define GEMM_BLOCKS (N_NODES / BM)     // 256
#define SCAN_BLOCKS 2048
#define BLOCK_U4    8192               // 128KB contiguous per scan block
#define QCAP        256                // per-warp queue capacity (mean ~16)

// -------- scratch (__device__ globals; zero-initialized at module load) ----
__device__ float g_h[N_NODES * C_OUT];      // 4 MB, h = x @ W
__device__ float g_asrc[N_NODES];
__device__ float g_adst[N_NODES];
__device__ int   g_cnt[N_NODES];            // per-column degree (excl. self)
__device__ int   g_list[N_NODES * MAX_DEG]; // 4 MB, CSC row lists

#define FULLM 0xFFFFFFFFu

// ---------------------------------------------------------------------
// Fused front kernel.
//  blocks [0, GEMM_BLOCKS):            h = x@W (4x4 micro-tile) + attn scores
//  blocks [GEMM_BLOCKS, +SCAN_BLOCKS): stream adj once (row-contiguous,
//                                      batch-4 LDG.128).
// Hot-path change vs R8: a nonzero no longer does ATOMG+dependent STG
// (~350cyc exposed chain that stalled the load stream). It pushes a packed
// (i<<13|j) into a PER-WARP smem queue (ATOMS, ~30cyc). After the stripe
// is consumed, the warp drains its queue: entries are lane-independent, so
// the 318-cyc ATOMG latency is paid once, fully overlapped across lanes.
// g_cnt is zeroed by the previous aggregate launch (zero-init at load).
// ---------------------------------------------------------------------
__global__ __launch_bounds__(256, 6) void fused_front_kernel(
    const float* __restrict__ x, const float* __restrict__ W,
    const float* __restrict__ adj,
    const float* __restrict__ att_src, const float* __restrict__ att_dst) {

    __shared__ union USm {
        struct { float xs[BK][BM]; float ws[BK][C_OUT]; } g;   // 10 KB
        struct { unsigned int q[8][QCAP]; int qcnt[8]; } s;    // 8 KB + 32B
    } su;

    int tid = threadIdx.x;

    if (blockIdx.x >= GEMM_BLOCKS) {
        // ======= adjacency scan: contiguous chunk, batch-4 LDG.128 =======
        const uint4* a4 = reinterpret_cast<const uint4*>(adj);
        const int sb   = blockIdx.x - GEMM_BLOCKS;
        const int base = sb * BLOCK_U4;          // contiguous 8192-uint4 chunk
        const int w    = tid >> 5;
        const int lane = tid & 31;

        if (lane == 0) su.s.qcnt[w] = 0;
        __syncwarp();

#pragma unroll
        for (int it = 0; it < 8; it++) {
            int qb = base + it * 1024 + tid;     // iter consumes 1024 uint4
            uint4 v0 = __ldcs(&a4[qb]);
            uint4 v1 = __ldcs(&a4[qb + 256]);
            uint4 v2 = __ldcs(&a4[qb + 512]);
            uint4 v3 = __ldcs(&a4[qb + 768]);
            uint4 vv[4] = {v0, v1, v2, v3};
#pragma unroll
            for (int u = 0; u < 4; u++) {
                uint4 v = vv[u];
                if ((v.x | v.y | v.z | v.w) == 0u) continue;
                int Q  = qb + u * 256;
                int i  = Q >> 11;                 // row (2048 uint4 per row)
                int j0 = (Q & 2047) << 2;         // first column of the 4
                unsigned int b[4] = {v.x, v.y, v.z, v.w};
#pragma unroll
                for (int t = 0; t < 4; t++) {
                    if (b[t] != 0u) {
                        int jj = j0 + t;
                        if (jj != i) {            // diagonal handled in aggregate
                            int p = atomicAdd(&su.s.qcnt[w], 1);   // smem, ~30cyc
                            if (p < QCAP) {
                                su.s.q[w][p] = ((unsigned)i << 13) | (unsigned)jj;
                            } else {              // overflow fallback (cold)
                                int pos = atomicAdd(&g_cnt[jj], 1);
                                if (pos < MAX_DEG) g_list[jj * MAX_DEG + pos] = i;
                            }
                        }
                    }
                }
            }
        }
        __syncwarp();

        // ---- drain: lane-parallel independent ATOMG + STG ----
        int n = su.s.qcnt[w];
        if (n > QCAP) n = QCAP;
        for (int e = lane; e < n; e += 32) {
            unsigned int v = su.s.q[w][e];
            int jj = v & 8191u;
            int i  = v >> 13;
            int pos = atomicAdd(&g_cnt[jj], 1);
            if (pos < MAX_DEG) g_list[jj * MAX_DEG + pos] = i;
        }
        return;
    }

    // ================= GEMM (BM=32, 4x4 micro-tile) + attention =================
    int row0 = blockIdx.x * BM;
    int tx = tid & 31;   // channel group: c = tx*4
    int ty = tid >> 5;   // row group: rows ty*4 .. ty*4+3 (warp == fixed ty)

    float acc[4][4];
#pragma unroll
    for (int r = 0; r < 4; r++)
#pragma unroll
        for (int c = 0; c < 4; c++) acc[r][c] = 0.0f;

    for (int k0 = 0; k0 < C_IN; k0 += BK) {
        {   // x tile: 32 rows x 16 k, one float2 per thread
            int r  = tid >> 3;          // 0..31
            int kk = (tid & 7) * 2;     // 0,2,..,14
            float2 v = *reinterpret_cast<const float2*>(
                &x[(row0 + r) * C_IN + k0 + kk]);
            su.g.xs[kk + 0][r] = v.x; su.g.xs[kk + 1][r] = v.y;
        }
        {   // W tile: 16 k x 128 c, two float4 per thread
            int kk = tid >> 5;              // 0..7
            int c  = (tid & 31) * 4;
            *reinterpret_cast<float4*>(&su.g.ws[kk][c]) =
                *reinterpret_cast<const float4*>(&W[(k0 + kk) * C_OUT + c]);
            *reinterpret_cast<float4*>(&su.g.ws[kk + 8][c]) =
                *reinterpret_cast<const float4*>(&W[(k0 + kk + 8) * C_OUT + c]);
        }
        __syncthreads();
#pragma unroll
        for (int kk = 0; kk < BK; kk++) {
            float4 b = *reinterpret_cast<const float4*>(&su.g.ws[kk][tx * 4]);
#pragma unroll
            for (int r = 0; r < 4; r++) {
                float a = su.g.xs[kk][ty * 4 + r];
                acc[r][0] += a * b.x;
                acc[r][1] += a * b.y;
                acc[r][2] += a * b.z;
                acc[r][3] += a * b.w;
            }
        }
        __syncthreads();
    }

    float4 as = *reinterpret_cast<const float4*>(&att_src[tx * 4]);
    float4 ad = *reinterpret_cast<const float4*>(&att_dst[tx * 4]);

#pragma unroll
    for (int r = 0; r < 4; r++) {
        int row = row0 + ty * 4 + r;
        float4 v = make_float4(acc[r][0], acc[r][1], acc[r][2], acc[r][3]);
        *reinterpret_cast<float4*>(&g_h[row * C_OUT + tx * 4]) = v;

        float s = v.x * as.x + v.y * as.y + v.z * as.z + v.w * as.w;
        float d = v.x * ad.x + v.y * ad.y + v.z * ad.z + v.w * ad.w;
#pragma unroll
        for (int o = 16; o > 0; o >>= 1) {
            s += __shfl_xor_sync(FULLM, s, o);
            d += __shfl_xor_sync(FULLM, d, o);
        }
        if (tx == 0) { g_asrc[row] = s; g_adst[row] = d; }
    }
}

// ---------------------------------------------------------------------
// Aggregate: one WARP per column (exact R5 version — best measured).
// Resets g_cnt for the next graph replay.
// ---------------------------------------------------------------------
__global__ __launch_bounds__(256) void aggregate_kernel(
    const float* __restrict__ bias, float* __restrict__ out) {
    int lane = threadIdx.x & 31;
    int j    = blockIdx.x * 8 + (threadIdx.x >> 5);   // column

    int cnt = g_cnt[j];
    if (cnt > MAX_DEG) cnt = MAX_DEG;
    float adst_j = g_adst[j];

    int   idx[4];
    float ew[4];
#pragma unroll
    for (int u = 0; u < 4; u++) {
        int d = lane + u * 32;
        if (d < cnt) {
            int i = g_list[j * MAX_DEG + d];
            idx[u] = i;
            float z = g_asrc[i] + adst_j;
            z = (z > 0.0f) ? z : NEG_SLOPE * z;
            ew[u] = __expf(z);
        } else {
            idx[u] = 0;
            ew[u] = 0.0f;
        }
    }
    if (lane == 0) g_cnt[j] = 0;   // reset for next graph replay

    // self-loop (reference SETS the diagonal to 1 -> always present)
    float zs = g_asrc[j] + adst_j;
    zs = (zs > 0.0f) ? zs : NEG_SLOPE * zs;
    float es = __expf(zs);

    float psum = ew[0] + ew[1] + ew[2] + ew[3];
#pragma unroll
    for (int o = 16; o > 0; o >>= 1) psum += __shfl_xor_sync(FULLM, psum, o);
    float inv = 1.0f / (psum + es);

    const float4* hj4 = reinterpret_cast<const float4*>(&g_h[j * C_OUT]);
    float4 h0 = hj4[lane];
    float4 acc0 = make_float4(es * h0.x, es * h0.y, es * h0.z, es * h0.w);
    float4 acc1 = make_float4(0.f, 0.f, 0.f, 0.f);

#pragma unroll
    for (int u = 0; u < 4; u++) {
        int base = u * 32;
        if (base >= cnt) break;
        int m = cnt - base;
        if (m > 32) m = 32;
        int s = 0;
        for (; s + 4 <= m; s += 4) {
            float e0 = __shfl_sync(FULLM, ew[u], s);
            float e1 = __shfl_sync(FULLM, ew[u], s + 1);
            float e2 = __shfl_sync(FULLM, ew[u], s + 2);
            float e3 = __shfl_sync(FULLM, ew[u], s + 3);
            int i0 = __shfl_sync(FULLM, idx[u], s);
            int i1 = __shfl_sync(FULLM, idx[u], s + 1);
            int i2 = __shfl_sync(FULLM, idx[u], s + 2);
            int i3 = __shfl_sync(FULLM, idx[u], s + 3);
            float4 a = reinterpret_cast<const float4*>(&g_h[i0 * C_OUT])[lane];
            float4 b = reinterpret_cast<const float4*>(&g_h[i1 * C_OUT])[lane];
            float4 cc = reinterpret_cast<const float4*>(&g_h[i2 * C_OUT])[lane];
            float4 dd = reinterpret_cast<const float4*>(&g_h[i3 * C_OUT])[lane];
            acc0.x += e0 * a.x;  acc0.y += e0 * a.y;  acc0.z += e0 * a.z;  acc0.w += e0 * a.w;
            acc1.x += e1 * b.x;  acc1.y += e1 * b.y;  acc1.z += e1 * b.z;  acc1.w += e1 * b.w;
            acc0.x += e2 * cc.x; acc0.y += e2 * cc.y; acc0.z += e2 * cc.z; acc0.w += e2 * cc.w;
            acc1.x += e3 * dd.x; acc1.y += e3 * dd.y; acc1.z += e3 * dd.z; acc1.w += e3 * dd.w;
        }
        for (; s < m; s++) {
            float e = __shfl_sync(FULLM, ew[u], s);
            int  i  = __shfl_sync(FULLM, idx[u], s);
            float4 a = reinterpret_cast<const float4*>(&g_h[i * C_OUT])[lane];
            acc0.x += e * a.x; acc0.y += e * a.y; acc0.z += e * a.z; acc0.w += e * a.w;
        }
    }

    float4 bv = reinterpret_cast<const float4*>(bias)[lane];
    float4 o;
    o.x = (acc0.x + acc1.x) * inv + bv.x;
    o.y = (acc0.y + acc1.y) * inv + bv.y;
    o.z = (acc0.z + acc1.z) * inv + bv.z;
    o.w = (acc0.w + acc1.w) * inv + bv.w;
    reinterpret_cast<float4*>(&out[j * C_OUT])[lane] = o;
}

// ---------------------------------------------------------------------
extern "C" void kernel_launch(void* const* d_in, const int* in_sizes, int n_in,
                              void* d_out, int out_size) {
    const float* x       = (const float*)d_in[0];
    const float* adj     = (const float*)d_in[1];
    const float* W       = (const float*)d_in[2];
    const float* att_src = (const float*)d_in[3];
    const float* att_dst = (const float*)d_in[4];
    const float* bias    = (const float*)d_in[5];
    float* out = (float*)d_out;

    fused_front_kernel<<<GEMM_BLOCKS + SCAN_BLOCKS, 256>>>(x, W, adj, att_src, att_dst);
    aggregate_kernel<<<N_NODES / 8, 256>>>(bias, out);
}

// round 11
// speedup vs baseline: 1.4337x; 1.0010x over previous
#include <cuda_runtime.h>
#include <cuda_bf16.h>
#include <math.h>
#include <stdint.h>

#define N_NODES   8192
#define C_IN      256
#define C_OUT     128
#define NEG_SLOPE 0.2f
#define MAX_DEG   128

#define BM 32
#define BK 16
#define GEMM_BLOCKS (N_NODES / BM)     // 256
#define SCAN_BLOCKS 2048
#define BLOCK_U4    8192               // 128KB contiguous per scan block
#define QCAP        256                // per-warp queue capacity (mean ~16)

// -------- scratch (__device__ globals; zero-initialized at module load) ----
__device__ float g_h[N_NODES * C_OUT];      // 4 MB, h = x @ W
__device__ float g_asrc[N_NODES];
__device__ float g_adst[N_NODES];
__device__ int   g_cnt[N_NODES];            // per-column degree (excl. self)
__device__ int   g_list[N_NODES * MAX_DEG]; // 4 MB, CSC row lists

#define FULLM 0xFFFFFFFFu

// ---------------------------------------------------------------------
// Fused front kernel (FROZEN — R10 configuration, best measured).
//  blocks [0, GEMM_BLOCKS):            h = x@W (4x4 micro-tile) + attn scores
//  blocks [GEMM_BLOCKS, +SCAN_BLOCKS): stream adj once; nonzeros go through
//    a per-warp smem queue (ATOMS ~30cyc) instead of ATOMG+dependent STG
//    (~350cyc exposed chain), drained lane-parallel after the stream.
// g_cnt is zeroed by the previous aggregate launch (zero-init at load).
// ---------------------------------------------------------------------
__global__ __launch_bounds__(256, 6) void fused_front_kernel(
    const float* __restrict__ x, const float* __restrict__ W,
    const float* __restrict__ adj,
    const float* __restrict__ att_src, const float* __restrict__ att_dst) {

    __shared__ union USm {
        struct { float xs[BK][BM]; float ws[BK][C_OUT]; } g;   // 10 KB
        struct { unsigned int q[8][QCAP]; int qcnt[8]; } s;    // 8 KB + 32B
    } su;

    int tid = threadIdx.x;

    if (blockIdx.x >= GEMM_BLOCKS) {
        // ======= adjacency scan: contiguous chunk, batch-4 LDG.128 =======
        const uint4* a4 = reinterpret_cast<const uint4*>(adj);
        const int sb   = blockIdx.x - GEMM_BLOCKS;
        const int base = sb * BLOCK_U4;          // contiguous 8192-uint4 chunk
        const int w    = tid >> 5;
        const int lane = tid & 31;

        if (lane == 0) su.s.qcnt[w] = 0;
        __syncwarp();

#pragma unroll
        for (int it = 0; it < 8; it++) {
            int qb = base + it * 1024 + tid;     // iter consumes 1024 uint4
            uint4 v0 = __ldcs(&a4[qb]);
            uint4 v1 = __ldcs(&a4[qb + 256]);
            uint4 v2 = __ldcs(&a4[qb + 512]);
            uint4 v3 = __ldcs(&a4[qb + 768]);
            uint4 vv[4] = {v0, v1, v2, v3};
#pragma unroll
            for (int u = 0; u < 4; u++) {
                uint4 v = vv[u];
                if ((v.x | v.y | v.z | v.w) == 0u) continue;
                int Q  = qb + u * 256;
                int i  = Q >> 11;                 // row (2048 uint4 per row)
                int j0 = (Q & 2047) << 2;         // first column of the 4
                unsigned int b[4] = {v.x, v.y, v.z, v.w};
#pragma unroll
                for (int t = 0; t < 4; t++) {
                    if (b[t] != 0u) {
                        int jj = j0 + t;
                        if (jj != i) {            // diagonal handled in aggregate
                            int p = atomicAdd(&su.s.qcnt[w], 1);   // smem, ~30cyc
                            if (p < QCAP) {
                                su.s.q[w][p] = ((unsigned)i << 13) | (unsigned)jj;
                            } else {              // overflow fallback (cold)
                                int pos = atomicAdd(&g_cnt[jj], 1);
                                if (pos < MAX_DEG) g_list[jj * MAX_DEG + pos] = i;
                            }
                        }
                    }
                }
            }
        }
        __syncwarp();

        // ---- drain: lane-parallel independent ATOMG + STG ----
        int n = su.s.qcnt[w];
        if (n > QCAP) n = QCAP;
        for (int e = lane; e < n; e += 32) {
            unsigned int v = su.s.q[w][e];
            int jj = v & 8191u;
            int i  = v >> 13;
            int pos = atomicAdd(&g_cnt[jj], 1);
            if (pos < MAX_DEG) g_list[jj * MAX_DEG + pos] = i;
        }
        return;
    }

    // ================= GEMM (BM=32, 4x4 micro-tile) + attention =================
    int row0 = blockIdx.x * BM;
    int tx = tid & 31;   // channel group: c = tx*4
    int ty = tid >> 5;   // row group: rows ty*4 .. ty*4+3 (warp == fixed ty)

    float acc[4][4];
#pragma unroll
    for (int r = 0; r < 4; r++)
#pragma unroll
        for (int c = 0; c < 4; c++) acc[r][c] = 0.0f;

    for (int k0 = 0; k0 < C_IN; k0 += BK) {
        {   // x tile: 32 rows x 16 k, one float2 per thread
            int r  = tid >> 3;          // 0..31
            int kk = (tid & 7) * 2;     // 0,2,..,14
            float2 v = *reinterpret_cast<const float2*>(
                &x[(row0 + r) * C_IN + k0 + kk]);
            su.g.xs[kk + 0][r] = v.x; su.g.xs[kk + 1][r] = v.y;
        }
        {   // W tile: 16 k x 128 c, two float4 per thread
            int kk = tid >> 5;              // 0..7
            int c  = (tid & 31) * 4;
            *reinterpret_cast<float4*>(&su.g.ws[kk][c]) =
                *reinterpret_cast<const float4*>(&W[(k0 + kk) * C_OUT + c]);
            *reinterpret_cast<float4*>(&su.g.ws[kk + 8][c]) =
                *reinterpret_cast<const float4*>(&W[(k0 + kk + 8) * C_OUT + c]);
        }
        __syncthreads();
#pragma unroll
        for (int kk = 0; kk < BK; kk++) {
            float4 b = *reinterpret_cast<const float4*>(&su.g.ws[kk][tx * 4]);
#pragma unroll
            for (int r = 0; r < 4; r++) {
                float a = su.g.xs[kk][ty * 4 + r];
                acc[r][0] += a * b.x;
                acc[r][1] += a * b.y;
                acc[r][2] += a * b.z;
                acc[r][3] += a * b.w;
            }
        }
        __syncthreads();
    }

    float4 as = *reinterpret_cast<const float4*>(&att_src[tx * 4]);
    float4 ad = *reinterpret_cast<const float4*>(&att_dst[tx * 4]);

#pragma unroll
    for (int r = 0; r < 4; r++) {
        int row = row0 + ty * 4 + r;
        float4 v = make_float4(acc[r][0], acc[r][1], acc[r][2], acc[r][3]);
        *reinterpret_cast<float4*>(&g_h[row * C_OUT + tx * 4]) = v;

        float s = v.x * as.x + v.y * as.y + v.z * as.z + v.w * as.w;
        float d = v.x * ad.x + v.y * ad.y + v.z * ad.z + v.w * ad.w;
#pragma unroll
        for (int o = 16; o > 0; o >>= 1) {
            s += __shfl_xor_sync(FULLM, s, o);
            d += __shfl_xor_sync(FULLM, d, o);
        }
        if (tx == 0) { g_asrc[row] = s; g_adst[row] = d; }
    }
}

// ---------------------------------------------------------------------
// Aggregate: one WARP per column, 8 gathers in flight per step.
// Lane d holds (idx, exp-weight) for edges d, d+32, d+64, d+96 in regs;
// inner loop broadcasts 8 edges, issues 8 independent float4 gathers
// back-to-back (MLP=8, halves the exposed L2-latency chain vs MLP=4),
// then accumulates into 2 accumulator quads.
// Resets g_cnt for the next graph replay.
// ---------------------------------------------------------------------
__global__ __launch_bounds__(256) void aggregate_kernel(
    const float* __restrict__ bias, float* __restrict__ out) {
    int lane = threadIdx.x & 31;
    int j    = blockIdx.x * 8 + (threadIdx.x >> 5);   // column

    int cnt = g_cnt[j];
    if (cnt > MAX_DEG) cnt = MAX_DEG;
    float adst_j = g_adst[j];

    int   idx[4];
    float ew[4];
#pragma unroll
    for (int u = 0; u < 4; u++) {
        int d = lane + u * 32;
        if (d < cnt) {
            int i = g_list[j * MAX_DEG + d];
            idx[u] = i;
            float z = g_asrc[i] + adst_j;
            z = (z > 0.0f) ? z : NEG_SLOPE * z;
            ew[u] = __expf(z);
        } else {
            idx[u] = 0;
            ew[u] = 0.0f;
        }
    }
    if (lane == 0) g_cnt[j] = 0;   // reset for next graph replay

    // self-loop (reference SETS the diagonal to 1 -> always present)
    float zs = g_asrc[j] + adst_j;
    zs = (zs > 0.0f) ? zs : NEG_SLOPE * zs;
    float es = __expf(zs);

    float psum = ew[0] + ew[1] + ew[2] + ew[3];
#pragma unroll
    for (int o = 16; o > 0; o >>= 1) psum += __shfl_xor_sync(FULLM, psum, o);
    float inv = 1.0f / (psum + es);

    const float4* hj4 = reinterpret_cast<const float4*>(&g_h[j * C_OUT]);
    float4 h0 = hj4[lane];
    float4 acc0 = make_float4(es * h0.x, es * h0.y, es * h0.z, es * h0.w);
    float4 acc1 = make_float4(0.f, 0.f, 0.f, 0.f);

#pragma unroll
    for (int u = 0; u < 4; u++) {
        int base = u * 32;
        if (base >= cnt) break;
        int m = cnt - base;
        if (m > 32) m = 32;
        int s = 0;
        for (; s + 8 <= m; s += 8) {
            float e0 = __shfl_sync(FULLM, ew[u], s);
            float e1 = __shfl_sync(FULLM, ew[u], s + 1);
            float e2 = __shfl_sync(FULLM, ew[u], s + 2);
            float e3 = __shfl_sync(FULLM, ew[u], s + 3);
            float e4 = __shfl_sync(FULLM, ew[u], s + 4);
            float e5 = __shfl_sync(FULLM, ew[u], s + 5);
            float e6 = __shfl_sync(FULLM, ew[u], s + 6);
            float e7 = __shfl_sync(FULLM, ew[u], s + 7);
            int i0 = __shfl_sync(FULLM, idx[u], s);
            int i1 = __shfl_sync(FULLM, idx[u], s + 1);
            int i2 = __shfl_sync(FULLM, idx[u], s + 2);
            int i3 = __shfl_sync(FULLM, idx[u], s + 3);
            int i4 = __shfl_sync(FULLM, idx[u], s + 4);
            int i5 = __shfl_sync(FULLM, idx[u], s + 5);
            int i6 = __shfl_sync(FULLM, idx[u], s + 6);
            int i7 = __shfl_sync(FULLM, idx[u], s + 7);
            float4 a0 = reinterpret_cast<const float4*>(&g_h[i0 * C_OUT])[lane];
            float4 a1 = reinterpret_cast<const float4*>(&g_h[i1 * C_OUT])[lane];
            float4 a2 = reinterpret_cast<const float4*>(&g_h[i2 * C_OUT])[lane];
            float4 a3 = reinterpret_cast<const float4*>(&g_h[i3 * C_OUT])[lane];
            float4 a4 = reinterpret_cast<const float4*>(&g_h[i4 * C_OUT])[lane];
            float4 a5 = reinterpret_cast<const float4*>(&g_h[i5 * C_OUT])[lane];
            float4 a6 = reinterpret_cast<const float4*>(&g_h[i6 * C_OUT])[lane];
            float4 a7 = reinterpret_cast<const float4*>(&g_h[i7 * C_OUT])[lane];
            acc0.x += e0 * a0.x; acc0.y += e0 * a0.y; acc0.z += e0 * a0.z; acc0.w += e0 * a0.w;
            acc1.x += e1 * a1.x; acc1.y += e1 * a1.y; acc1.z += e1 * a1.z; acc1.w += e1 * a1.w;
            acc0.x += e2 * a2.x; acc0.y += e2 * a2.y; acc0.z += e2 * a2.z; acc0.w += e2 * a2.w;
            acc1.x += e3 * a3.x; acc1.y += e3 * a3.y; acc1.z += e3 * a3.z; acc1.w += e3 * a3.w;
            acc0.x += e4 * a4.x; acc0.y += e4 * a4.y; acc0.z += e4 * a4.z; acc0.w += e4 * a4.w;
            acc1.x += e5 * a5.x; acc1.y += e5 * a5.y; acc1.z += e5 * a5.z; acc1.w += e5 * a5.w;
            acc0.x += e6 * a6.x; acc0.y += e6 * a6.y; acc0.z += e6 * a6.z; acc0.w += e6 * a6.w;
            acc1.x += e7 * a7.x; acc1.y += e7 * a7.y; acc1.z += e7 * a7.z; acc1.w += e7 * a7.w;
        }
        for (; s < m; s++) {
            float e = __shfl_sync(FULLM, ew[u], s);
            int  i  = __shfl_sync(FULLM, idx[u], s);
            float4 a = reinterpret_cast<const float4*>(&g_h[i * C_OUT])[lane];
            acc0.x += e * a.x; acc0.y += e * a.y; acc0.z += e * a.z; acc0.w += e * a.w;
        }
    }

    float4 bv = reinterpret_cast<const float4*>(bias)[lane];
    float4 o;
    o.x = (acc0.x + acc1.x) * inv + bv.x;
    o.y = (acc0.y + acc1.y) * inv + bv.y;
    o.z = (acc0.z + acc1.z) * inv + bv.z;
    o.w = (acc0.w + acc1.w) * inv + bv.w;
    reinterpret_cast<float4*>(&out[j * C_OUT])[lane] = o;
}

// ---------------------------------------------------------------------
extern "C" void kernel_launch(void* const* d_in, const int* in_sizes, int n_in,
                              void* d_out, int out_size) {
    const float* x       = (const float*)d_in[0];
    const float* adj     = (const float*)d_in[1];
    const float* W       = (const float*)d_in[2];
    const float* att_src = (const float*)d_in[3];
    const float* att_dst = (const float*)d_in[4];
    const float* bias    = (const float*)d_in[5];
    float* out = (float*)d_out;

    fused_front_kernel<<<GEMM_BLOCKS + SCAN_BLOCKS, 256>>>(x, W, adj, att_src, att_dst);
    aggregate_kernel<<<N_NODES / 8, 256>>>(bias, out);
}